// round 4
// baseline (speedup 1.0000x reference)
#include <cuda_runtime.h>
#include <cuda_bf16.h>
#include <cstdint>

#define BATCH   4
#define SEQ     8192
#define DIM     512
#define HEADS   8
#define NTOK    32768
#define QKVW    1536
#define SCALE_Q 0.125f
#define MTILES  256
#define PADT    133

// ---------------- scratch ----------------
__device__ __align__(16) __nv_bfloat16 g_ah[(size_t)NTOK * DIM];
__device__ __align__(16) __nv_bfloat16 g_al[(size_t)NTOK * DIM];
__device__ __align__(16) __nv_bfloat16 g_oh[(size_t)NTOK * DIM];
__device__ __align__(16) __nv_bfloat16 g_ol[(size_t)NTOK * DIM];
__device__ __align__(16) __nv_bfloat16 g_wqh[(size_t)DIM * QKVW];
__device__ __align__(16) __nv_bfloat16 g_wql[(size_t)DIM * QKVW];
__device__ __align__(16) __nv_bfloat16 g_woh[(size_t)DIM * DIM];
__device__ __align__(16) __nv_bfloat16 g_wol[(size_t)DIM * DIM];
__device__ float g_qkv[(size_t)NTOK * QKVW];   // q region holds exp(q*scale)
__device__ float g_ctx[BATCH * HEADS * 64 * 64];
__device__ float g_qsum[BATCH * DIM];

// ---------------- PTX helpers (family-target-safe only) ----------------
__device__ __forceinline__ uint32_t s2u(const void* p) {
    uint32_t a;
    asm("{ .reg .u64 t; cvta.to.shared.u64 t, %1; cvt.u32.u64 %0, t; }" : "=r"(a) : "l"(p));
    return a;
}
#define CP16(d, s)                                                            \
    asm volatile("cp.async.cg.shared.global [%0], [%1], 16;" :: "r"(d), "l"(s) : "memory")
#define CPCOMMIT() asm volatile("cp.async.commit_group;" ::: "memory")
#define CPWAIT2()  asm volatile("cp.async.wait_group 2;" ::: "memory")
#define LDSM_X4(r, a)                                                         \
    asm volatile("ldmatrix.sync.aligned.m8n8.x4.shared.b16 {%0,%1,%2,%3}, [%4];" \
        : "=r"((r)[0]), "=r"((r)[1]), "=r"((r)[2]), "=r"((r)[3]) : "r"(a))
#define LDSM_X2T(r, a)                                                        \
    asm volatile("ldmatrix.sync.aligned.m8n8.x2.trans.shared.b16 {%0,%1}, [%2];" \
        : "=r"((r)[0]), "=r"((r)[1]) : "r"(a))
#define MMA(d, a, b)                                                          \
    asm volatile("mma.sync.aligned.m16n8k16.row.col.f32.bf16.bf16.f32 "       \
        "{%0,%1,%2,%3},{%4,%5,%6,%7},{%8,%9},{%0,%1,%2,%3};"                  \
        : "+f"((d)[0]), "+f"((d)[1]), "+f"((d)[2]), "+f"((d)[3])              \
        : "r"((a)[0]), "r"((a)[1]), "r"((a)[2]), "r"((a)[3]),                 \
          "r"((b)[0]), "r"((b)[1]))

// ---------------- init ----------------
__global__ void init_kernel() {
    int i = blockIdx.x * 256 + threadIdx.x;
    if (i < BATCH * HEADS * 64 * 64) g_ctx[i] = 0.f;
    if (i < BATCH * DIM) g_qsum[i] = 0.f;
}

// ---------------- LayerNorm + transpose -> row-major bf16 hi/lo ------------
__global__ __launch_bounds__(256) void ln_kernel(
    const float* __restrict__ x, const float* __restrict__ lw,
    const float* __restrict__ lb)
{
    extern __shared__ float s[];               // [512][33]
    __shared__ float s_mu[32], s_rs[32];
    int tid = threadIdx.x;
    int token0 = blockIdx.x * 32;
    int b = token0 >> 13;
    int n0 = token0 & (SEQ - 1);
    const float* xb = x + (size_t)b * DIM * SEQ;

    #pragma unroll 4
    for (int i = 0; i < 64; i++) {
        int idx = i * 256 + tid;
        int d = idx >> 5, j = idx & 31;
        s[d * 33 + j] = xb[(size_t)d * SEQ + n0 + j];
    }
    __syncthreads();

    int w = tid >> 5, lane = tid & 31;
    for (int t = 0; t < 4; t++) {
        int j = w * 4 + t;
        float sum = 0.f, sq = 0.f;
        #pragma unroll
        for (int d = lane; d < DIM; d += 32) {
            float v = s[d * 33 + j];
            sum += v; sq += v * v;
        }
        #pragma unroll
        for (int o = 16; o; o >>= 1) {
            sum += __shfl_xor_sync(0xffffffffu, sum, o);
            sq  += __shfl_xor_sync(0xffffffffu, sq, o);
        }
        if (lane == 0) {
            float mu = sum * (1.f / DIM);
            float var = sq * (1.f / DIM) - mu * mu;
            s_mu[j] = mu;
            s_rs[j] = rsqrtf(var + 1e-5f);
        }
    }
    __syncthreads();

    #pragma unroll
    for (int it = 0; it < 8; it++) {
        int idx = it * 256 + tid;
        int g = idx & 63, j = idx >> 6;
        int d0 = g * 8;
        float mu = s_mu[j], rs = s_rs[j];
        union { __nv_bfloat16 h[8]; uint4 u; } ph, pl;
        #pragma unroll
        for (int i = 0; i < 8; i++) {
            int d = d0 + i;
            float v = (s[d * 33 + j] - mu) * rs * lw[d] + lb[d];
            __nv_bfloat16 hv = __float2bfloat16(v);
            ph.h[i] = hv;
            pl.h[i] = __float2bfloat16(v - __bfloat162float(hv));
        }
        size_t off = (size_t)(token0 + j) * DIM + d0;
        *(uint4*)&g_ah[off] = ph.u;
        *(uint4*)&g_al[off] = pl.u;
    }
}

// ---------------- weight fp32 -> bf16 hi/lo ---------------------------------
__global__ __launch_bounds__(256) void wconv_kernel(
    const float* __restrict__ wq, const float* __restrict__ wo)
{
    int stride = gridDim.x * 256;
    for (int i = blockIdx.x * 256 + threadIdx.x; i < DIM * QKVW; i += stride) {
        float v = wq[i];
        __nv_bfloat16 h = __float2bfloat16(v);
        g_wqh[i] = h;
        g_wql[i] = __float2bfloat16(v - __bfloat162float(h));
    }
    for (int i = blockIdx.x * 256 + threadIdx.x; i < DIM * DIM; i += stride) {
        float v = wo[i];
        __nv_bfloat16 h = __float2bfloat16(v);
        g_woh[i] = h;
        g_wol[i] = __float2bfloat16(v - __bfloat162float(h));
    }
}

// ---------------- split-bf16 HMMA GEMM: C = A @ B, K=512 --------------------
// mode 0: qkv output; q columns (<512) stored as exp(v*scale) + column sums.
// mode 1: out[b][dout][n] + bias (transposed store).
#define STAGE   20992
#define NSTAGES 4
__global__ __launch_bounds__(256) void mma_gemm_kernel(
    const __nv_bfloat16* __restrict__ Ah, const __nv_bfloat16* __restrict__ Al,
    const __nv_bfloat16* __restrict__ Bh, const __nv_bfloat16* __restrict__ Bl,
    float* __restrict__ C, const float* __restrict__ bias, int ldb, int mode)
{
    extern __shared__ char smem[];
    uint32_t sb = s2u(smem);
    int tid = threadIdx.x, lane = tid & 31, wid = tid >> 5;
    int m0 = blockIdx.y * 128, n0 = blockIdx.x * 128;
    int wm = (wid >> 2) * 64, wn = (wid & 3) * 32;

    int ar = tid >> 1, ah8 = (tid & 1) * 8;
    int bkr = tid >> 4, bn8 = (tid & 15) * 8;
    const __nv_bfloat16* Agh = Ah + (size_t)(m0 + ar) * DIM + ah8;
    const __nv_bfloat16* Agl = Al + (size_t)(m0 + ar) * DIM + ah8;
    const __nv_bfloat16* Bgh = Bh + (size_t)bkr * ldb + n0 + bn8;
    const __nv_bfloat16* Bgl = Bl + (size_t)bkr * ldb + n0 + bn8;
    uint32_t dAh = sb + ar * 48 + ah8 * 2;
    uint32_t dAl = dAh + 6144;
    uint32_t dBh = sb + 12288 + bkr * 272 + bn8 * 2;
    uint32_t dBl = dBh + 4352;

    uint32_t aAddr[4], bAddr[4];
    #pragma unroll
    for (int mi = 0; mi < 4; mi++)
        aAddr[mi] = sb + (wm + mi * 16 + (lane & 15)) * 48 + (lane >> 4) * 16;
    #pragma unroll
    for (int ni = 0; ni < 4; ni++)
        bAddr[ni] = sb + 12288 + (lane & 15) * 272 + (wn + ni * 8) * 2;

    float d[4][4][4];
    #pragma unroll
    for (int mi = 0; mi < 4; mi++)
        #pragma unroll
        for (int ni = 0; ni < 4; ni++)
            #pragma unroll
            for (int r = 0; r < 4; r++) d[mi][ni][r] = 0.f;

    // prologue: stages 0..2
    #pragma unroll
    for (int p = 0; p < 3; p++) {
        uint32_t so = p * STAGE;
        CP16(dAh + so, Agh + p * 16);
        CP16(dAl + so, Agl + p * 16);
        CP16(dBh + so, Bgh + (size_t)p * 16 * ldb);
        CP16(dBl + so, Bgl + (size_t)p * 16 * ldb);
        CPCOMMIT();
    }

    for (int kk = 0; kk < 32; kk++) {
        CPWAIT2();
        __syncthreads();
        if (kk + 3 < 32) {
            uint32_t so = ((kk + 3) & 3) * STAGE;
            CP16(dAh + so, Agh + (kk + 3) * 16);
            CP16(dAl + so, Agl + (kk + 3) * 16);
            CP16(dBh + so, Bgh + (size_t)(kk + 3) * 16 * ldb);
            CP16(dBl + so, Bgl + (size_t)(kk + 3) * 16 * ldb);
        }
        CPCOMMIT();

        uint32_t so = (kk & 3) * STAGE;
        uint32_t ah[4][4], al[4][4], bh[4][2], bl[4][2];
        #pragma unroll
        for (int mi = 0; mi < 4; mi++) {
            LDSM_X4(ah[mi], aAddr[mi] + so);
            LDSM_X4(al[mi], aAddr[mi] + so + 6144);
        }
        #pragma unroll
        for (int ni = 0; ni < 4; ni++) {
            LDSM_X2T(bh[ni], bAddr[ni] + so);
            LDSM_X2T(bl[ni], bAddr[ni] + so + 4352);
        }
        // three passes: 16-deep accumulator reuse distance (no RAW stalls)
        #pragma unroll
        for (int mi = 0; mi < 4; mi++)
            #pragma unroll
            for (int ni = 0; ni < 4; ni++)
                MMA(d[mi][ni], ah[mi], bh[ni]);
        #pragma unroll
        for (int mi = 0; mi < 4; mi++)
            #pragma unroll
            for (int ni = 0; ni < 4; ni++)
                MMA(d[mi][ni], ah[mi], bl[ni]);
        #pragma unroll
        for (int mi = 0; mi < 4; mi++)
            #pragma unroll
            for (int ni = 0; ni < 4; ni++)
                MMA(d[mi][ni], al[mi], bh[ni]);
    }

    if (mode == 0) {
        bool isq = (n0 < 512);
        float* qs = (float*)smem;              // column partial sums (q tiles)
        if (isq) {
            __syncthreads();
            if (tid < 128) qs[tid] = 0.f;
            __syncthreads();
        }
        #pragma unroll
        for (int mi = 0; mi < 4; mi++) {
            int r0 = m0 + wm + mi * 16 + (lane >> 2);
            #pragma unroll
            for (int ni = 0; ni < 4; ni++) {
                int cl = wn + ni * 8 + (lane & 3) * 2;
                int c0 = n0 + cl;
                float v0 = d[mi][ni][0], v1 = d[mi][ni][1];
                float v2 = d[mi][ni][2], v3 = d[mi][ni][3];
                if (isq) {
                    v0 = __expf(v0 * SCALE_Q); v1 = __expf(v1 * SCALE_Q);
                    v2 = __expf(v2 * SCALE_Q); v3 = __expf(v3 * SCALE_Q);
                    atomicAdd(&qs[cl],     v0 + v2);
                    atomicAdd(&qs[cl + 1], v1 + v3);
                }
                *(float2*)&C[(size_t)r0 * ldb + c0]       = make_float2(v0, v1);
                *(float2*)&C[(size_t)(r0 + 8) * ldb + c0] = make_float2(v2, v3);
            }
        }
        if (isq) {
            __syncthreads();
            if (tid < 128)
                atomicAdd(&g_qsum[(m0 >> 13) * DIM + n0 + tid], qs[tid]);
        }
    } else {
        __syncthreads();
        float* st = (float*)smem;             // [128][PADT]
        #pragma unroll
        for (int mi = 0; mi < 4; mi++) {
            int r0 = wm + mi * 16 + (lane >> 2);
            #pragma unroll
            for (int ni = 0; ni < 4; ni++) {
                int c0 = wn + ni * 8 + (lane & 3) * 2;
                st[r0 * PADT + c0]           = d[mi][ni][0];
                st[r0 * PADT + c0 + 1]       = d[mi][ni][1];
                st[(r0 + 8) * PADT + c0]     = d[mi][ni][2];
                st[(r0 + 8) * PADT + c0 + 1] = d[mi][ni][3];
            }
        }
        __syncthreads();
        int b = m0 >> 13, nn0 = m0 & (SEQ - 1);
        float* dst = C + (size_t)b * DIM * SEQ + (size_t)n0 * SEQ + nn0;
        for (int idx = tid; idx < 16384; idx += 256) {
            int r = idx >> 7;
            int c = idx & 127;
            dst[(size_t)r * SEQ + c] = st[c * PADT + r] + bias[n0 + r];
        }
    }
}

// ---------------- k softmax + context accumulation --------------------------
__global__ __launch_bounds__(256) void ctx_kernel()
{
    __shared__ float kb[16][64];
    __shared__ float vb[16][64];
    int tid = threadIdx.x;
    int h = blockIdx.y;
    int tok0 = blockIdx.x * 512;
    int b = tok0 >> 13;
    int d = tid & 63, eg = tid >> 6;
    int ltt = tid >> 4, ld4 = (tid & 15) * 4;
    float acc[16] = {};

    for (int t0 = 0; t0 < 512; t0 += 16) {
        size_t base = (size_t)(tok0 + t0 + ltt) * QKVW + h * 64 + ld4;
        *(float4*)&kb[ltt][ld4] = *(const float4*)&g_qkv[base + 512];
        *(float4*)&vb[ltt][ld4] = *(const float4*)&g_qkv[base + 1024];
        __syncthreads();
        {
            int w = tid >> 5, lane = tid & 31;
            #pragma unroll
            for (int u = 0; u < 2; u++) {
                int tt = w * 2 + u;
                float e0 = __expf(kb[tt][lane]);
                float e1 = __expf(kb[tt][lane + 32]);
                float su = e0 + e1;
                #pragma unroll
                for (int o = 16; o; o >>= 1) su += __shfl_xor_sync(0xffffffffu, su, o);
                float inv = 1.f / su;
                kb[tt][lane] = e0 * inv;
                kb[tt][lane + 32] = e1 * inv;
            }
        }
        __syncthreads();
        const float4* vrow;
        #pragma unroll
        for (int tt = 0; tt < 16; tt++) {
            float a = kb[tt][d];
            vrow = (const float4*)&vb[tt][eg * 16];
            float4 w0 = vrow[0], w1 = vrow[1], w2 = vrow[2], w3 = vrow[3];
            acc[0]  += a * w0.x; acc[1]  += a * w0.y; acc[2]  += a * w0.z; acc[3]  += a * w0.w;
            acc[4]  += a * w1.x; acc[5]  += a * w1.y; acc[6]  += a * w1.z; acc[7]  += a * w1.w;
            acc[8]  += a * w2.x; acc[9]  += a * w2.y; acc[10] += a * w2.z; acc[11] += a * w2.w;
            acc[12] += a * w3.x; acc[13] += a * w3.y; acc[14] += a * w3.z; acc[15] += a * w3.w;
        }
        __syncthreads();
    }
    float* cdst = &g_ctx[((b * HEADS + h) * 64 + d) * 64 + eg * 16];
    #pragma unroll
    for (int c = 0; c < 16; c++) atomicAdd(&cdst[c], acc[c]);
}

// ---------------- o = qexp*rq @ ctx ; write row-major hi/lo -----------------
__global__ __launch_bounds__(256) void oproj_kernel()
{
    __shared__ float cs[64][64];
    __shared__ float qt[64][65];
    __shared__ float rq[64];
    int tid = threadIdx.x;
    int h = blockIdx.y;
    int tok0 = blockIdx.x * 64;
    int b = tok0 >> 13;

    const float* csrc = &g_ctx[(b * HEADS + h) * 64 * 64];
    for (int i = tid; i < 4096; i += 256) cs[i >> 6][i & 63] = csrc[i];
    if (tid < 64) rq[tid] = 1.f / g_qsum[b * DIM + h * 64 + tid];
    __syncthreads();

    for (int i = tid; i < 64 * 64; i += 256) {
        int t = i >> 6, dd = i & 63;
        // q already stored as exp(q*scale)
        qt[t][dd] = g_qkv[(size_t)(tok0 + t) * QKVW + h * 64 + dd] * rq[dd];
    }
    __syncthreads();

    int tx = tid & 15, ty = tid >> 4;
    float acc[4][4] = {};
    #pragma unroll
    for (int dd = 0; dd < 64; dd++) {
        float a[4], bb[4];
        #pragma unroll
        for (int i = 0; i < 4; i++) a[i] = qt[ty * 4 + i][dd];
        #pragma unroll
        for (int j = 0; j < 4; j++) bb[j] = cs[dd][tx * 4 + j];
        #pragma unroll
        for (int i = 0; i < 4; i++)
            #pragma unroll
            for (int j = 0; j < 4; j++)
                acc[i][j] += a[i] * bb[j];
    }
    #pragma unroll
    for (int i = 0; i < 4; i++) {
        int t = tok0 + ty * 4 + i;
        union { __nv_bfloat16 h2[4]; uint2 u; } ph, pl;
        #pragma unroll
        for (int j = 0; j < 4; j++) {
            __nv_bfloat16 hv = __float2bfloat16(acc[i][j]);
            ph.h2[j] = hv;
            pl.h2[j] = __float2bfloat16(acc[i][j] - __bfloat162float(hv));
        }
        size_t off = (size_t)t * DIM + h * 64 + tx * 4;
        *(uint2*)&g_oh[off] = ph.u;
        *(uint2*)&g_ol[off] = pl.u;
    }
}

// ---------------- launch ------------------------------------------------------
extern "C" void kernel_launch(void* const* d_in, const int* in_sizes, int n_in,
                              void* d_out, int out_size)
{
    const float* x     = (const float*)d_in[0];
    const float* ln_w  = (const float*)d_in[1];
    const float* ln_b  = (const float*)d_in[2];
    const float* w_qkv = (const float*)d_in[3];
    const float* w_out = (const float*)d_in[4];
    const float* b_out = (const float*)d_in[5];
    float* out = (float*)d_out;

    __nv_bfloat16 *p_ah, *p_al, *p_oh, *p_ol, *p_wqh, *p_wql, *p_woh, *p_wol;
    float* p_qkv;
    cudaGetSymbolAddress((void**)&p_ah, g_ah);
    cudaGetSymbolAddress((void**)&p_al, g_al);
    cudaGetSymbolAddress((void**)&p_oh, g_oh);
    cudaGetSymbolAddress((void**)&p_ol, g_ol);
    cudaGetSymbolAddress((void**)&p_wqh, g_wqh);
    cudaGetSymbolAddress((void**)&p_wql, g_wql);
    cudaGetSymbolAddress((void**)&p_woh, g_woh);
    cudaGetSymbolAddress((void**)&p_wol, g_wol);
    cudaGetSymbolAddress((void**)&p_qkv, g_qkv);

    const int LN_SMEM   = 512 * 33 * 4;
    const int GEMM_SMEM = NSTAGES * STAGE;    // 83968 >= epilogue 68096
    cudaFuncSetAttribute(ln_kernel, cudaFuncAttributeMaxDynamicSharedMemorySize, LN_SMEM);
    cudaFuncSetAttribute(mma_gemm_kernel, cudaFuncAttributeMaxDynamicSharedMemorySize, GEMM_SMEM);

    init_kernel<<<(BATCH * HEADS * 64 * 64 + 255) / 256, 256>>>();
    ln_kernel<<<NTOK / 32, 256, LN_SMEM>>>(x, ln_w, ln_b);
    wconv_kernel<<<1024, 256>>>(w_qkv, w_out);
    mma_gemm_kernel<<<dim3(QKVW / 128, MTILES), 256, GEMM_SMEM>>>(
        p_ah, p_al, p_wqh, p_wql, p_qkv, nullptr, QKVW, 0);
    ctx_kernel<<<dim3(NTOK / 512, HEADS), 256>>>();
    oproj_kernel<<<dim3(NTOK / 64, HEADS), 256>>>();
    mma_gemm_kernel<<<dim3(DIM / 128, MTILES), 256, GEMM_SMEM>>>(
        p_oh, p_ol, p_woh, p_wol, out, b_out, DIM, 1);
}

// round 5
// speedup vs baseline: 1.1469x; 1.1469x over previous
#include <cuda_runtime.h>
#include <cuda_fp16.h>
#include <cstdint>

#define BATCH   4
#define SEQ     8192
#define DIM     512
#define HEADS   8
#define NTOK    32768
#define QKVW    1536
#define SCALE_Q 0.125f
#define MTILES  256
#define PADT    133

// ---------------- scratch ----------------
__device__ __align__(16) __half g_ah[(size_t)NTOK * DIM];
__device__ __align__(16) __half g_al[(size_t)NTOK * DIM];
__device__ __align__(16) __half g_oh[(size_t)NTOK * DIM];
__device__ __align__(16) __half g_ol[(size_t)NTOK * DIM];
__device__ __align__(16) __half g_wq[(size_t)DIM * QKVW];
__device__ __align__(16) __half g_wo[(size_t)DIM * DIM];
__device__ float g_qkv[(size_t)NTOK * QKVW];   // q region holds exp(q*scale)
__device__ float g_ctx[BATCH * HEADS * 64 * 64];
__device__ float g_qsum[BATCH * DIM];

// ---------------- PTX helpers (family-target-safe only) ----------------
__device__ __forceinline__ uint32_t s2u(const void* p) {
    uint32_t a;
    asm("{ .reg .u64 t; cvta.to.shared.u64 t, %1; cvt.u32.u64 %0, t; }" : "=r"(a) : "l"(p));
    return a;
}
#define CP16(d, s)                                                            \
    asm volatile("cp.async.cg.shared.global [%0], [%1], 16;" :: "r"(d), "l"(s) : "memory")
#define CPCOMMIT() asm volatile("cp.async.commit_group;" ::: "memory")
#define CPWAIT1()  asm volatile("cp.async.wait_group 1;" ::: "memory")
#define LDSM_X4(r, a)                                                         \
    asm volatile("ldmatrix.sync.aligned.m8n8.x4.shared.b16 {%0,%1,%2,%3}, [%4];" \
        : "=r"((r)[0]), "=r"((r)[1]), "=r"((r)[2]), "=r"((r)[3]) : "r"(a))
#define LDSM_X2T(r, a)                                                        \
    asm volatile("ldmatrix.sync.aligned.m8n8.x2.trans.shared.b16 {%0,%1}, [%2];" \
        : "=r"((r)[0]), "=r"((r)[1]) : "r"(a))
#define MMA(d, a, b)                                                          \
    asm volatile("mma.sync.aligned.m16n8k16.row.col.f32.f16.f16.f32 "         \
        "{%0,%1,%2,%3},{%4,%5,%6,%7},{%8,%9},{%0,%1,%2,%3};"                  \
        : "+f"((d)[0]), "+f"((d)[1]), "+f"((d)[2]), "+f"((d)[3])              \
        : "r"((a)[0]), "r"((a)[1]), "r"((a)[2]), "r"((a)[3]),                 \
          "r"((b)[0]), "r"((b)[1]))

// ---------------- init ----------------
__global__ void init_kernel() {
    int i = blockIdx.x * 256 + threadIdx.x;
    if (i < BATCH * HEADS * 64 * 64) g_ctx[i] = 0.f;
    if (i < BATCH * DIM) g_qsum[i] = 0.f;
}

// ---------------- LayerNorm + transpose -> row-major fp16 hi/lo ------------
__global__ __launch_bounds__(256) void ln_kernel(
    const float* __restrict__ x, const float* __restrict__ lw,
    const float* __restrict__ lb)
{
    extern __shared__ float s[];               // [512][33]
    __shared__ float s_mu[32], s_rs[32];
    int tid = threadIdx.x;
    int token0 = blockIdx.x * 32;
    int b = token0 >> 13;
    int n0 = token0 & (SEQ - 1);
    const float* xb = x + (size_t)b * DIM * SEQ;

    #pragma unroll 4
    for (int i = 0; i < 64; i++) {
        int idx = i * 256 + tid;
        int d = idx >> 5, j = idx & 31;
        s[d * 33 + j] = xb[(size_t)d * SEQ + n0 + j];
    }
    __syncthreads();

    int w = tid >> 5, lane = tid & 31;
    for (int t = 0; t < 4; t++) {
        int j = w * 4 + t;
        float sum = 0.f, sq = 0.f;
        #pragma unroll
        for (int d = lane; d < DIM; d += 32) {
            float v = s[d * 33 + j];
            sum += v; sq += v * v;
        }
        #pragma unroll
        for (int o = 16; o; o >>= 1) {
            sum += __shfl_xor_sync(0xffffffffu, sum, o);
            sq  += __shfl_xor_sync(0xffffffffu, sq, o);
        }
        if (lane == 0) {
            float mu = sum * (1.f / DIM);
            float var = sq * (1.f / DIM) - mu * mu;
            s_mu[j] = mu;
            s_rs[j] = rsqrtf(var + 1e-5f);
        }
    }
    __syncthreads();

    #pragma unroll
    for (int it = 0; it < 8; it++) {
        int idx = it * 256 + tid;
        int g = idx & 63, j = idx >> 6;
        int d0 = g * 8;
        float mu = s_mu[j], rs = s_rs[j];
        union { __half h[8]; uint4 u; } ph, pl;
        #pragma unroll
        for (int i = 0; i < 8; i++) {
            int d = d0 + i;
            float v = (s[d * 33 + j] - mu) * rs * lw[d] + lb[d];
            __half hv = __float2half_rn(v);
            ph.h[i] = hv;
            pl.h[i] = __float2half_rn(v - __half2float(hv));
        }
        size_t off = (size_t)(token0 + j) * DIM + d0;
        *(uint4*)&g_ah[off] = ph.u;
        *(uint4*)&g_al[off] = pl.u;
    }
}

// ---------------- weight fp32 -> single fp16 ---------------------------------
__global__ __launch_bounds__(256) void wconv_kernel(
    const float* __restrict__ wq, const float* __restrict__ wo)
{
    int stride = gridDim.x * 256;
    for (int i = blockIdx.x * 256 + threadIdx.x; i < DIM * QKVW; i += stride)
        g_wq[i] = __float2half_rn(wq[i]);
    for (int i = blockIdx.x * 256 + threadIdx.x; i < DIM * DIM; i += stride)
        g_wo[i] = __float2half_rn(wo[i]);
}

// ---------------- split-fp16 HMMA GEMM: C = (Ah+Al) @ B, K=512 --------------
// mode 0: qkv output; q columns (<512) stored as exp(v*scale) + column sums.
// mode 1: out[b][dout][n] + bias (transposed store).
#define STAGE 16640
__global__ __launch_bounds__(256) void mma_gemm_kernel(
    const __half* __restrict__ Ah, const __half* __restrict__ Al,
    const __half* __restrict__ B,
    float* __restrict__ C, const float* __restrict__ bias, int ldb, int mode)
{
    extern __shared__ char smem[];
    uint32_t sb = s2u(smem);
    int tid = threadIdx.x, lane = tid & 31, wid = tid >> 5;
    int m0 = blockIdx.y * 128, n0 = blockIdx.x * 128;
    int wm = (wid >> 2) * 64, wn = (wid & 3) * 32;

    int ar = tid >> 1, ah8 = (tid & 1) * 8;
    int bkr = tid >> 4, bn8 = (tid & 15) * 8;
    const __half* Agh = Ah + (size_t)(m0 + ar) * DIM + ah8;
    const __half* Agl = Al + (size_t)(m0 + ar) * DIM + ah8;
    const __half* Bg  = B + (size_t)bkr * ldb + n0 + bn8;
    uint32_t dAh = sb + ar * 48 + ah8 * 2;
    uint32_t dAl = dAh + 6144;
    uint32_t dB  = sb + 12288 + bkr * 272 + bn8 * 2;

    uint32_t aAddr[4], bAddr[4];
    #pragma unroll
    for (int mi = 0; mi < 4; mi++)
        aAddr[mi] = sb + (wm + mi * 16 + (lane & 15)) * 48 + (lane >> 4) * 16;
    #pragma unroll
    for (int ni = 0; ni < 4; ni++)
        bAddr[ni] = sb + 12288 + (lane & 15) * 272 + (wn + ni * 8) * 2;

    float d[4][4][4];
    #pragma unroll
    for (int mi = 0; mi < 4; mi++)
        #pragma unroll
        for (int ni = 0; ni < 4; ni++)
            #pragma unroll
            for (int r = 0; r < 4; r++) d[mi][ni][r] = 0.f;

    // prologue: stages 0,1
    #pragma unroll
    for (int p = 0; p < 2; p++) {
        uint32_t so = p * STAGE;
        CP16(dAh + so, Agh + p * 16);
        CP16(dAl + so, Agl + p * 16);
        CP16(dB  + so, Bg  + (size_t)p * 16 * ldb);
        CPCOMMIT();
    }

    for (int kk = 0; kk < 32; kk++) {
        CPWAIT1();
        __syncthreads();
        if (kk + 2 < 32) {
            uint32_t so = ((kk + 2) % 3) * STAGE;
            CP16(dAh + so, Agh + (kk + 2) * 16);
            CP16(dAl + so, Agl + (kk + 2) * 16);
            CP16(dB  + so, Bg  + (size_t)(kk + 2) * 16 * ldb);
        }
        CPCOMMIT();

        uint32_t so = (kk % 3) * STAGE;
        uint32_t ah[4][4], al[4][4], bh[4][2];
        #pragma unroll
        for (int mi = 0; mi < 4; mi++) {
            LDSM_X4(ah[mi], aAddr[mi] + so);
            LDSM_X4(al[mi], aAddr[mi] + so + 6144);
        }
        #pragma unroll
        for (int ni = 0; ni < 4; ni++)
            LDSM_X2T(bh[ni], bAddr[ni] + so);
        #pragma unroll
        for (int mi = 0; mi < 4; mi++)
            #pragma unroll
            for (int ni = 0; ni < 4; ni++) {
                MMA(d[mi][ni], ah[mi], bh[ni]);
                MMA(d[mi][ni], al[mi], bh[ni]);
            }
    }

    if (mode == 0) {
        bool isq = (n0 < 512);
        float* qs = (float*)smem;              // column partial sums (q tiles)
        if (isq) {
            __syncthreads();
            if (tid < 128) qs[tid] = 0.f;
            __syncthreads();
        }
        #pragma unroll
        for (int mi = 0; mi < 4; mi++) {
            int r0 = m0 + wm + mi * 16 + (lane >> 2);
            #pragma unroll
            for (int ni = 0; ni < 4; ni++) {
                int cl = wn + ni * 8 + (lane & 3) * 2;
                int c0 = n0 + cl;
                float v0 = d[mi][ni][0], v1 = d[mi][ni][1];
                float v2 = d[mi][ni][2], v3 = d[mi][ni][3];
                if (isq) {
                    v0 = __expf(v0 * SCALE_Q); v1 = __expf(v1 * SCALE_Q);
                    v2 = __expf(v2 * SCALE_Q); v3 = __expf(v3 * SCALE_Q);
                    atomicAdd(&qs[cl],     v0 + v2);
                    atomicAdd(&qs[cl + 1], v1 + v3);
                }
                *(float2*)&C[(size_t)r0 * ldb + c0]       = make_float2(v0, v1);
                *(float2*)&C[(size_t)(r0 + 8) * ldb + c0] = make_float2(v2, v3);
            }
        }
        if (isq) {
            __syncthreads();
            if (tid < 128)
                atomicAdd(&g_qsum[(m0 >> 13) * DIM + n0 + tid], qs[tid]);
        }
    } else {
        __syncthreads();
        float* st = (float*)smem;             // [128][PADT]
        #pragma unroll
        for (int mi = 0; mi < 4; mi++) {
            int r0 = wm + mi * 16 + (lane >> 2);
            #pragma unroll
            for (int ni = 0; ni < 4; ni++) {
                int c0 = wn + ni * 8 + (lane & 3) * 2;
                st[r0 * PADT + c0]           = d[mi][ni][0];
                st[r0 * PADT + c0 + 1]       = d[mi][ni][1];
                st[(r0 + 8) * PADT + c0]     = d[mi][ni][2];
                st[(r0 + 8) * PADT + c0 + 1] = d[mi][ni][3];
            }
        }
        __syncthreads();
        int b = m0 >> 13, nn0 = m0 & (SEQ - 1);
        float* dst = C + (size_t)b * DIM * SEQ + (size_t)n0 * SEQ + nn0;
        for (int idx = tid; idx < 16384; idx += 256) {
            int r = idx >> 7;
            int c = idx & 127;
            dst[(size_t)r * SEQ + c] = st[c * PADT + r] + bias[n0 + r];
        }
    }
}

// ---------------- k softmax + context accumulation --------------------------
__global__ __launch_bounds__(256) void ctx_kernel()
{
    __shared__ float kb[16][64];
    __shared__ float vb[16][64];
    int tid = threadIdx.x;
    int h = blockIdx.y;
    int tok0 = blockIdx.x * 512;
    int b = tok0 >> 13;
    int d = tid & 63, eg = tid >> 6;
    int ltt = tid >> 4, ld4 = (tid & 15) * 4;
    float acc[16] = {};

    for (int t0 = 0; t0 < 512; t0 += 16) {
        size_t base = (size_t)(tok0 + t0 + ltt) * QKVW + h * 64 + ld4;
        *(float4*)&kb[ltt][ld4] = *(const float4*)&g_qkv[base + 512];
        *(float4*)&vb[ltt][ld4] = *(const float4*)&g_qkv[base + 1024];
        __syncthreads();
        {
            int w = tid >> 5, lane = tid & 31;
            #pragma unroll
            for (int u = 0; u < 2; u++) {
                int tt = w * 2 + u;
                float e0 = __expf(kb[tt][lane]);
                float e1 = __expf(kb[tt][lane + 32]);
                float su = e0 + e1;
                #pragma unroll
                for (int o = 16; o; o >>= 1) su += __shfl_xor_sync(0xffffffffu, su, o);
                float inv = 1.f / su;
                kb[tt][lane] = e0 * inv;
                kb[tt][lane + 32] = e1 * inv;
            }
        }
        __syncthreads();
        #pragma unroll
        for (int tt = 0; tt < 16; tt++) {
            float a = kb[tt][d];
            const float4* vrow = (const float4*)&vb[tt][eg * 16];
            float4 w0 = vrow[0], w1 = vrow[1], w2 = vrow[2], w3 = vrow[3];
            acc[0]  += a * w0.x; acc[1]  += a * w0.y; acc[2]  += a * w0.z; acc[3]  += a * w0.w;
            acc[4]  += a * w1.x; acc[5]  += a * w1.y; acc[6]  += a * w1.z; acc[7]  += a * w1.w;
            acc[8]  += a * w2.x; acc[9]  += a * w2.y; acc[10] += a * w2.z; acc[11] += a * w2.w;
            acc[12] += a * w3.x; acc[13] += a * w3.y; acc[14] += a * w3.z; acc[15] += a * w3.w;
        }
        __syncthreads();
    }
    float* cdst = &g_ctx[((b * HEADS + h) * 64 + d) * 64 + eg * 16];
    #pragma unroll
    for (int c = 0; c < 16; c++) atomicAdd(&cdst[c], acc[c]);
}

// ---------------- o = qexp*rq @ ctx ; write row-major fp16 hi/lo ------------
__global__ __launch_bounds__(256) void oproj_kernel()
{
    __shared__ float cs[64][64];
    __shared__ float qt[64][65];
    __shared__ float rq[64];
    int tid = threadIdx.x;
    int h = blockIdx.y;
    int tok0 = blockIdx.x * 64;
    int b = tok0 >> 13;

    const float* csrc = &g_ctx[(b * HEADS + h) * 64 * 64];
    for (int i = tid; i < 4096; i += 256) cs[i >> 6][i & 63] = csrc[i];
    if (tid < 64) rq[tid] = 1.f / g_qsum[b * DIM + h * 64 + tid];
    __syncthreads();

    for (int i = tid; i < 64 * 64; i += 256) {
        int t = i >> 6, dd = i & 63;
        qt[t][dd] = g_qkv[(size_t)(tok0 + t) * QKVW + h * 64 + dd] * rq[dd];
    }
    __syncthreads();

    int tx = tid & 15, ty = tid >> 4;
    float acc[4][4] = {};
    #pragma unroll
    for (int dd = 0; dd < 64; dd++) {
        float a[4], bb[4];
        #pragma unroll
        for (int i = 0; i < 4; i++) a[i] = qt[ty * 4 + i][dd];
        #pragma unroll
        for (int j = 0; j < 4; j++) bb[j] = cs[dd][tx * 4 + j];
        #pragma unroll
        for (int i = 0; i < 4; i++)
            #pragma unroll
            for (int j = 0; j < 4; j++)
                acc[i][j] += a[i] * bb[j];
    }
    #pragma unroll
    for (int i = 0; i < 4; i++) {
        int t = tok0 + ty * 4 + i;
        union { __half h2[4]; uint2 u; } ph, pl;
        #pragma unroll
        for (int j = 0; j < 4; j++) {
            __half hv = __float2half_rn(acc[i][j]);
            ph.h2[j] = hv;
            pl.h2[j] = __float2half_rn(acc[i][j] - __half2float(hv));
        }
        size_t off = (size_t)t * DIM + h * 64 + tx * 4;
        *(uint2*)&g_oh[off] = ph.u;
        *(uint2*)&g_ol[off] = pl.u;
    }
}

// ---------------- launch ------------------------------------------------------
extern "C" void kernel_launch(void* const* d_in, const int* in_sizes, int n_in,
                              void* d_out, int out_size)
{
    const float* x     = (const float*)d_in[0];
    const float* ln_w  = (const float*)d_in[1];
    const float* ln_b  = (const float*)d_in[2];
    const float* w_qkv = (const float*)d_in[3];
    const float* w_out = (const float*)d_in[4];
    const float* b_out = (const float*)d_in[5];
    float* out = (float*)d_out;

    __half *p_ah, *p_al, *p_oh, *p_ol, *p_wq, *p_wo;
    float* p_qkv;
    cudaGetSymbolAddress((void**)&p_ah, g_ah);
    cudaGetSymbolAddress((void**)&p_al, g_al);
    cudaGetSymbolAddress((void**)&p_oh, g_oh);
    cudaGetSymbolAddress((void**)&p_ol, g_ol);
    cudaGetSymbolAddress((void**)&p_wq, g_wq);
    cudaGetSymbolAddress((void**)&p_wo, g_wo);
    cudaGetSymbolAddress((void**)&p_qkv, g_qkv);

    const int LN_SMEM   = 512 * 33 * 4;
    const int GEMM_SMEM = 128 * PADT * 4;    // 68096 >= 3*STAGE = 49920
    cudaFuncSetAttribute(ln_kernel, cudaFuncAttributeMaxDynamicSharedMemorySize, LN_SMEM);
    cudaFuncSetAttribute(mma_gemm_kernel, cudaFuncAttributeMaxDynamicSharedMemorySize, GEMM_SMEM);

    init_kernel<<<(BATCH * HEADS * 64 * 64 + 255) / 256, 256>>>();
    ln_kernel<<<NTOK / 32, 256, LN_SMEM>>>(x, ln_w, ln_b);
    wconv_kernel<<<1024, 256>>>(w_qkv, w_out);
    mma_gemm_kernel<<<dim3(QKVW / 128, MTILES), 256, GEMM_SMEM>>>(
        p_ah, p_al, p_wq, p_qkv, nullptr, QKVW, 0);
    ctx_kernel<<<dim3(NTOK / 512, HEADS), 256>>>();
    oproj_kernel<<<dim3(NTOK / 64, HEADS), 256>>>();
    mma_gemm_kernel<<<dim3(DIM / 128, MTILES), 256, GEMM_SMEM>>>(
        p_oh, p_ol, p_wo, out, b_out, DIM, 1);
}

// round 6
// speedup vs baseline: 1.1638x; 1.0147x over previous
#include <cuda_runtime.h>
#include <cuda_fp16.h>
#include <cstdint>

#define BATCH   4
#define SEQ     8192
#define DIM     512
#define HEADS   8
#define NTOK    32768
#define QKVW    1536
#define SCALE_Q 0.125f
#define MTILES  256
#define PADT    133

// ---------------- scratch ----------------
__device__ __align__(16) __half g_ah[(size_t)NTOK * DIM];
__device__ __align__(16) __half g_al[(size_t)NTOK * DIM];
__device__ __align__(16) __half g_oh[(size_t)NTOK * DIM];
__device__ __align__(16) __half g_ol[(size_t)NTOK * DIM];
__device__ __align__(16) __half g_wq[(size_t)DIM * QKVW];
__device__ __align__(16) __half g_wo[(size_t)DIM * DIM];
__device__ float g_qkv[(size_t)NTOK * QKVW];   // q region holds exp(q*scale)
__device__ float g_ctx[BATCH * HEADS * 64 * 64];
__device__ float g_qsum[BATCH * DIM];

// ---------------- PTX helpers (family-target-safe only) ----------------
__device__ __forceinline__ uint32_t s2u(const void* p) {
    uint32_t a;
    asm("{ .reg .u64 t; cvta.to.shared.u64 t, %1; cvt.u32.u64 %0, t; }" : "=r"(a) : "l"(p));
    return a;
}
#define CP16(d, s)                                                            \
    asm volatile("cp.async.cg.shared.global [%0], [%1], 16;" :: "r"(d), "l"(s) : "memory")
#define CPCOMMIT() asm volatile("cp.async.commit_group;" ::: "memory")
#define CPWAIT1()  asm volatile("cp.async.wait_group 1;" ::: "memory")
#define LDSM_X4(r, a)                                                         \
    asm volatile("ldmatrix.sync.aligned.m8n8.x4.shared.b16 {%0,%1,%2,%3}, [%4];" \
        : "=r"((r)[0]), "=r"((r)[1]), "=r"((r)[2]), "=r"((r)[3]) : "r"(a))
#define LDSM_X2T(r, a)                                                        \
    asm volatile("ldmatrix.sync.aligned.m8n8.x2.trans.shared.b16 {%0,%1}, [%2];" \
        : "=r"((r)[0]), "=r"((r)[1]) : "r"(a))
#define MMA(d, a, b)                                                          \
    asm volatile("mma.sync.aligned.m16n8k16.row.col.f32.f16.f16.f32 "         \
        "{%0,%1,%2,%3},{%4,%5,%6,%7},{%8,%9},{%0,%1,%2,%3};"                  \
        : "+f"((d)[0]), "+f"((d)[1]), "+f"((d)[2]), "+f"((d)[3])              \
        : "r"((a)[0]), "r"((a)[1]), "r"((a)[2]), "r"((a)[3]),                 \
          "r"((b)[0]), "r"((b)[1]))

// ---------------- init ----------------
__global__ void init_kernel() {
    int i = blockIdx.x * 256 + threadIdx.x;
    if (i < BATCH * HEADS * 64 * 64) g_ctx[i] = 0.f;
    if (i < BATCH * DIM) g_qsum[i] = 0.f;
}

// ---------------- LayerNorm + transpose -> row-major fp16 hi/lo ------------
__global__ __launch_bounds__(256) void ln_kernel(
    const float* __restrict__ x, const float* __restrict__ lw,
    const float* __restrict__ lb)
{
    extern __shared__ float s[];               // [512][33]
    __shared__ float s_mu[32], s_rs[32];
    int tid = threadIdx.x;
    int token0 = blockIdx.x * 32;
    int b = token0 >> 13;
    int n0 = token0 & (SEQ - 1);
    const float* xb = x + (size_t)b * DIM * SEQ;

    #pragma unroll 4
    for (int i = 0; i < 64; i++) {
        int idx = i * 256 + tid;
        int d = idx >> 5, j = idx & 31;
        s[d * 33 + j] = xb[(size_t)d * SEQ + n0 + j];
    }
    __syncthreads();

    int w = tid >> 5, lane = tid & 31;
    for (int t = 0; t < 4; t++) {
        int j = w * 4 + t;
        float sum = 0.f, sq = 0.f;
        #pragma unroll
        for (int d = lane; d < DIM; d += 32) {
            float v = s[d * 33 + j];
            sum += v; sq += v * v;
        }
        #pragma unroll
        for (int o = 16; o; o >>= 1) {
            sum += __shfl_xor_sync(0xffffffffu, sum, o);
            sq  += __shfl_xor_sync(0xffffffffu, sq, o);
        }
        if (lane == 0) {
            float mu = sum * (1.f / DIM);
            float var = sq * (1.f / DIM) - mu * mu;
            s_mu[j] = mu;
            s_rs[j] = rsqrtf(var + 1e-5f);
        }
    }
    __syncthreads();

    #pragma unroll
    for (int it = 0; it < 8; it++) {
        int idx = it * 256 + tid;
        int g = idx & 63, j = idx >> 6;
        int d0 = g * 8;
        float mu = s_mu[j], rs = s_rs[j];
        union { __half h[8]; uint4 u; } ph, pl;
        #pragma unroll
        for (int i = 0; i < 8; i++) {
            int d = d0 + i;
            float v = (s[d * 33 + j] - mu) * rs * lw[d] + lb[d];
            __half hv = __float2half_rn(v);
            ph.h[i] = hv;
            pl.h[i] = __float2half_rn(v - __half2float(hv));
        }
        size_t off = (size_t)(token0 + j) * DIM + d0;
        *(uint4*)&g_ah[off] = ph.u;
        *(uint4*)&g_al[off] = pl.u;
    }
}

// ---------------- weight fp32 -> single fp16 ---------------------------------
__global__ __launch_bounds__(256) void wconv_kernel(
    const float* __restrict__ wq, const float* __restrict__ wo)
{
    int stride = gridDim.x * 256;
    for (int i = blockIdx.x * 256 + threadIdx.x; i < DIM * QKVW; i += stride)
        g_wq[i] = __float2half_rn(wq[i]);
    for (int i = blockIdx.x * 256 + threadIdx.x; i < DIM * DIM; i += stride)
        g_wo[i] = __float2half_rn(wo[i]);
}

// ---------------- split-fp16 HMMA GEMM: C = (Ah+Al) @ B, K=512 --------------
// BK=32 stages (two 16-k slices per stage): 16 iterations, deep prefetch.
// mode 0: qkv output; q columns (<512) stored as exp(v*scale) + column sums.
// mode 1: out[b][dout][n] + bias (transposed store).
#define SLICE 16640
#define STAGE (2 * SLICE)        // 33280
__global__ __launch_bounds__(256) void mma_gemm_kernel(
    const __half* __restrict__ Ah, const __half* __restrict__ Al,
    const __half* __restrict__ B,
    float* __restrict__ C, const float* __restrict__ bias, int ldb, int mode)
{
    extern __shared__ char smem[];
    uint32_t sb = s2u(smem);
    int tid = threadIdx.x, lane = tid & 31, wid = tid >> 5;
    int m0 = blockIdx.y * 128, n0 = blockIdx.x * 128;
    int wm = (wid >> 2) * 64, wn = (wid & 3) * 32;

    int ar = tid >> 1, ah8 = (tid & 1) * 8;
    int bkr = tid >> 4, bn8 = (tid & 15) * 8;
    const __half* Agh = Ah + (size_t)(m0 + ar) * DIM + ah8;
    const __half* Agl = Al + (size_t)(m0 + ar) * DIM + ah8;
    const __half* Bg  = B + (size_t)bkr * ldb + n0 + bn8;
    uint32_t dAh = sb + ar * 48 + ah8 * 2;
    uint32_t dAl = dAh + 6144;
    uint32_t dB  = sb + 12288 + bkr * 272 + bn8 * 2;

    uint32_t aAddr[4], bAddr[4];
    #pragma unroll
    for (int mi = 0; mi < 4; mi++)
        aAddr[mi] = sb + (wm + mi * 16 + (lane & 15)) * 48 + (lane >> 4) * 16;
    #pragma unroll
    for (int ni = 0; ni < 4; ni++)
        bAddr[ni] = sb + 12288 + (lane & 15) * 272 + (wn + ni * 8) * 2;

    float d[4][4][4];
    #pragma unroll
    for (int mi = 0; mi < 4; mi++)
        #pragma unroll
        for (int ni = 0; ni < 4; ni++)
            #pragma unroll
            for (int r = 0; r < 4; r++) d[mi][ni][r] = 0.f;

    // prologue: stages 0,1 (each stage = 2 k16 slices)
    #pragma unroll
    for (int p = 0; p < 2; p++) {
        #pragma unroll
        for (int s = 0; s < 2; s++) {
            uint32_t so = p * STAGE + s * SLICE;
            int ks = p * 2 + s;
            CP16(dAh + so, Agh + ks * 16);
            CP16(dAl + so, Agl + ks * 16);
            CP16(dB  + so, Bg  + (size_t)ks * 16 * ldb);
        }
        CPCOMMIT();
    }

    for (int kk = 0; kk < 16; kk++) {
        CPWAIT1();
        __syncthreads();
        if (kk + 2 < 16) {
            #pragma unroll
            for (int s = 0; s < 2; s++) {
                uint32_t so = ((kk + 2) % 3) * STAGE + s * SLICE;
                int ks = (kk + 2) * 2 + s;
                CP16(dAh + so, Agh + ks * 16);
                CP16(dAl + so, Agl + ks * 16);
                CP16(dB  + so, Bg  + (size_t)ks * 16 * ldb);
            }
        }
        CPCOMMIT();

        #pragma unroll
        for (int s = 0; s < 2; s++) {
            uint32_t so = (kk % 3) * STAGE + s * SLICE;
            uint32_t ah[4][4], al[4][4], bh[4][2];
            #pragma unroll
            for (int mi = 0; mi < 4; mi++) {
                LDSM_X4(ah[mi], aAddr[mi] + so);
                LDSM_X4(al[mi], aAddr[mi] + so + 6144);
            }
            #pragma unroll
            for (int ni = 0; ni < 4; ni++)
                LDSM_X2T(bh[ni], bAddr[ni] + so);
            #pragma unroll
            for (int mi = 0; mi < 4; mi++)
                #pragma unroll
                for (int ni = 0; ni < 4; ni++) {
                    MMA(d[mi][ni], ah[mi], bh[ni]);
                    MMA(d[mi][ni], al[mi], bh[ni]);
                }
        }
    }

    if (mode == 0) {
        bool isq = (n0 < 512);
        float* qs = (float*)smem;              // column partial sums (q tiles)
        if (isq) {
            __syncthreads();
            if (tid < 128) qs[tid] = 0.f;
            __syncthreads();
        }
        #pragma unroll
        for (int mi = 0; mi < 4; mi++) {
            int r0 = m0 + wm + mi * 16 + (lane >> 2);
            #pragma unroll
            for (int ni = 0; ni < 4; ni++) {
                int cl = wn + ni * 8 + (lane & 3) * 2;
                int c0 = n0 + cl;
                float v0 = d[mi][ni][0], v1 = d[mi][ni][1];
                float v2 = d[mi][ni][2], v3 = d[mi][ni][3];
                if (isq) {
                    v0 = __expf(v0 * SCALE_Q); v1 = __expf(v1 * SCALE_Q);
                    v2 = __expf(v2 * SCALE_Q); v3 = __expf(v3 * SCALE_Q);
                    atomicAdd(&qs[cl],     v0 + v2);
                    atomicAdd(&qs[cl + 1], v1 + v3);
                }
                *(float2*)&C[(size_t)r0 * ldb + c0]       = make_float2(v0, v1);
                *(float2*)&C[(size_t)(r0 + 8) * ldb + c0] = make_float2(v2, v3);
            }
        }
        if (isq) {
            __syncthreads();
            if (tid < 128)
                atomicAdd(&g_qsum[(m0 >> 13) * DIM + n0 + tid], qs[tid]);
        }
    } else {
        __syncthreads();
        float* st = (float*)smem;             // [128][PADT]
        #pragma unroll
        for (int mi = 0; mi < 4; mi++) {
            int r0 = wm + mi * 16 + (lane >> 2);
            #pragma unroll
            for (int ni = 0; ni < 4; ni++) {
                int c0 = wn + ni * 8 + (lane & 3) * 2;
                st[r0 * PADT + c0]           = d[mi][ni][0];
                st[r0 * PADT + c0 + 1]       = d[mi][ni][1];
                st[(r0 + 8) * PADT + c0]     = d[mi][ni][2];
                st[(r0 + 8) * PADT + c0 + 1] = d[mi][ni][3];
            }
        }
        __syncthreads();
        int b = m0 >> 13, nn0 = m0 & (SEQ - 1);
        float* dst = C + (size_t)b * DIM * SEQ + (size_t)n0 * SEQ + nn0;
        for (int idx = tid; idx < 16384; idx += 256) {
            int r = idx >> 7;
            int c = idx & 127;
            dst[(size_t)r * SEQ + c] = st[c * PADT + r] + bias[n0 + r];
        }
    }
}

// ---------------- k softmax + context accumulation --------------------------
__global__ __launch_bounds__(256) void ctx_kernel()
{
    __shared__ float kb[16][64];
    __shared__ float vb[16][64];
    int tid = threadIdx.x;
    int h = blockIdx.y;
    int tok0 = blockIdx.x * 512;
    int b = tok0 >> 13;
    int d = tid & 63, eg = tid >> 6;
    int ltt = tid >> 4, ld4 = (tid & 15) * 4;
    float acc[16] = {};

    for (int t0 = 0; t0 < 512; t0 += 16) {
        size_t base = (size_t)(tok0 + t0 + ltt) * QKVW + h * 64 + ld4;
        *(float4*)&kb[ltt][ld4] = *(const float4*)&g_qkv[base + 512];
        *(float4*)&vb[ltt][ld4] = *(const float4*)&g_qkv[base + 1024];
        __syncthreads();
        {
            int w = tid >> 5, lane = tid & 31;
            #pragma unroll
            for (int u = 0; u < 2; u++) {
                int tt = w * 2 + u;
                float e0 = __expf(kb[tt][lane]);
                float e1 = __expf(kb[tt][lane + 32]);
                float su = e0 + e1;
                #pragma unroll
                for (int o = 16; o; o >>= 1) su += __shfl_xor_sync(0xffffffffu, su, o);
                float inv = 1.f / su;
                kb[tt][lane] = e0 * inv;
                kb[tt][lane + 32] = e1 * inv;
            }
        }
        __syncthreads();
        #pragma unroll
        for (int tt = 0; tt < 16; tt++) {
            float a = kb[tt][d];
            const float4* vrow = (const float4*)&vb[tt][eg * 16];
            float4 w0 = vrow[0], w1 = vrow[1], w2 = vrow[2], w3 = vrow[3];
            acc[0]  += a * w0.x; acc[1]  += a * w0.y; acc[2]  += a * w0.z; acc[3]  += a * w0.w;
            acc[4]  += a * w1.x; acc[5]  += a * w1.y; acc[6]  += a * w1.z; acc[7]  += a * w1.w;
            acc[8]  += a * w2.x; acc[9]  += a * w2.y; acc[10] += a * w2.z; acc[11] += a * w2.w;
            acc[12] += a * w3.x; acc[13] += a * w3.y; acc[14] += a * w3.z; acc[15] += a * w3.w;
        }
        __syncthreads();
    }
    float* cdst = &g_ctx[((b * HEADS + h) * 64 + d) * 64 + eg * 16];
    #pragma unroll
    for (int c = 0; c < 16; c++) atomicAdd(&cdst[c], acc[c]);
}

// ---------------- o = qexp*rq @ ctx ; write row-major fp16 hi/lo ------------
__global__ __launch_bounds__(256) void oproj_kernel()
{
    __shared__ float cs[64][64];
    __shared__ float qt[64][65];
    __shared__ float rq[64];
    int tid = threadIdx.x;
    int h = blockIdx.y;
    int tok0 = blockIdx.x * 64;
    int b = tok0 >> 13;

    const float* csrc = &g_ctx[(b * HEADS + h) * 64 * 64];
    for (int i = tid; i < 4096; i += 256) cs[i >> 6][i & 63] = csrc[i];
    if (tid < 64) rq[tid] = 1.f / g_qsum[b * DIM + h * 64 + tid];
    __syncthreads();

    for (int i = tid; i < 64 * 64; i += 256) {
        int t = i >> 6, dd = i & 63;
        qt[t][dd] = g_qkv[(size_t)(tok0 + t) * QKVW + h * 64 + dd] * rq[dd];
    }
    __syncthreads();

    int tx = tid & 15, ty = tid >> 4;
    float acc[4][4] = {};
    #pragma unroll
    for (int dd = 0; dd < 64; dd++) {
        float a[4], bb[4];
        #pragma unroll
        for (int i = 0; i < 4; i++) a[i] = qt[ty * 4 + i][dd];
        #pragma unroll
        for (int j = 0; j < 4; j++) bb[j] = cs[dd][tx * 4 + j];
        #pragma unroll
        for (int i = 0; i < 4; i++)
            #pragma unroll
            for (int j = 0; j < 4; j++)
                acc[i][j] += a[i] * bb[j];
    }
    #pragma unroll
    for (int i = 0; i < 4; i++) {
        int t = tok0 + ty * 4 + i;
        union { __half h2[4]; uint2 u; } ph, pl;
        #pragma unroll
        for (int j = 0; j < 4; j++) {
            __half hv = __float2half_rn(acc[i][j]);
            ph.h2[j] = hv;
            pl.h2[j] = __float2half_rn(acc[i][j] - __half2float(hv));
        }
        size_t off = (size_t)t * DIM + h * 64 + tx * 4;
        *(uint2*)&g_oh[off] = ph.u;
        *(uint2*)&g_ol[off] = pl.u;
    }
}

// ---------------- launch ------------------------------------------------------
extern "C" void kernel_launch(void* const* d_in, const int* in_sizes, int n_in,
                              void* d_out, int out_size)
{
    const float* x     = (const float*)d_in[0];
    const float* ln_w  = (const float*)d_in[1];
    const float* ln_b  = (const float*)d_in[2];
    const float* w_qkv = (const float*)d_in[3];
    const float* w_out = (const float*)d_in[4];
    const float* b_out = (const float*)d_in[5];
    float* out = (float*)d_out;

    __half *p_ah, *p_al, *p_oh, *p_ol, *p_wq, *p_wo;
    float* p_qkv;
    cudaGetSymbolAddress((void**)&p_ah, g_ah);
    cudaGetSymbolAddress((void**)&p_al, g_al);
    cudaGetSymbolAddress((void**)&p_oh, g_oh);
    cudaGetSymbolAddress((void**)&p_ol, g_ol);
    cudaGetSymbolAddress((void**)&p_wq, g_wq);
    cudaGetSymbolAddress((void**)&p_wo, g_wo);
    cudaGetSymbolAddress((void**)&p_qkv, g_qkv);

    const int LN_SMEM   = 512 * 33 * 4;
    const int GEMM_SMEM = 3 * STAGE;         // 99840 >= epilogue 68096
    cudaFuncSetAttribute(ln_kernel, cudaFuncAttributeMaxDynamicSharedMemorySize, LN_SMEM);
    cudaFuncSetAttribute(mma_gemm_kernel, cudaFuncAttributeMaxDynamicSharedMemorySize, GEMM_SMEM);

    init_kernel<<<(BATCH * HEADS * 64 * 64 + 255) / 256, 256>>>();
    ln_kernel<<<NTOK / 32, 256, LN_SMEM>>>(x, ln_w, ln_b);
    wconv_kernel<<<1024, 256>>>(w_qkv, w_out);
    mma_gemm_kernel<<<dim3(QKVW / 128, MTILES), 256, GEMM_SMEM>>>(
        p_ah, p_al, p_wq, p_qkv, nullptr, QKVW, 0);
    ctx_kernel<<<dim3(NTOK / 512, HEADS), 256>>>();
    oproj_kernel<<<dim3(NTOK / 64, HEADS), 256>>>();
    mma_gemm_kernel<<<dim3(DIM / 128, MTILES), 256, GEMM_SMEM>>>(
        p_oh, p_ol, p_wo, out, b_out, DIM, 1);
}

// round 7
// speedup vs baseline: 1.4463x; 1.2427x over previous
#include <cuda_runtime.h>
#include <cuda_fp16.h>
#include <cstdint>

#define BATCH   4
#define SEQ     8192
#define DIM     512
#define HEADS   8
#define NTOK    32768
#define QKVW    1536
#define SCALE_Q 0.125f
#define MTILES  256
#define PADT    133

// ---------------- scratch ----------------
__device__ __align__(16) __half g_a[(size_t)NTOK * DIM];
__device__ __align__(16) __half g_o[(size_t)NTOK * DIM];
__device__ __align__(16) __half g_wq[(size_t)DIM * QKVW];
__device__ __align__(16) __half g_wo[(size_t)DIM * DIM];
__device__ float g_qkv[(size_t)NTOK * QKVW];   // q region holds exp(q*scale)
__device__ float g_ctx[BATCH * HEADS * 64 * 64];
__device__ float g_qsum[BATCH * DIM];

// ---------------- PTX helpers (family-target-safe only) ----------------
__device__ __forceinline__ uint32_t s2u(const void* p) {
    uint32_t a;
    asm("{ .reg .u64 t; cvta.to.shared.u64 t, %1; cvt.u32.u64 %0, t; }" : "=r"(a) : "l"(p));
    return a;
}
#define CP16(d, s)                                                            \
    asm volatile("cp.async.cg.shared.global [%0], [%1], 16;" :: "r"(d), "l"(s) : "memory")
#define CPCOMMIT() asm volatile("cp.async.commit_group;" ::: "memory")
#define CPWAIT1()  asm volatile("cp.async.wait_group 1;" ::: "memory")
#define LDSM_X4(r, a)                                                         \
    asm volatile("ldmatrix.sync.aligned.m8n8.x4.shared.b16 {%0,%1,%2,%3}, [%4];" \
        : "=r"((r)[0]), "=r"((r)[1]), "=r"((r)[2]), "=r"((r)[3]) : "r"(a))
#define LDSM_X2T(r, a)                                                        \
    asm volatile("ldmatrix.sync.aligned.m8n8.x2.trans.shared.b16 {%0,%1}, [%2];" \
        : "=r"((r)[0]), "=r"((r)[1]) : "r"(a))
#define MMA(d, a, b)                                                          \
    asm volatile("mma.sync.aligned.m16n8k16.row.col.f32.f16.f16.f32 "         \
        "{%0,%1,%2,%3},{%4,%5,%6,%7},{%8,%9},{%0,%1,%2,%3};"                  \
        : "+f"((d)[0]), "+f"((d)[1]), "+f"((d)[2]), "+f"((d)[3])              \
        : "r"((a)[0]), "r"((a)[1]), "r"((a)[2]), "r"((a)[3]),                 \
          "r"((b)[0]), "r"((b)[1]))

// ---------------- init ----------------
__global__ void init_kernel() {
    int i = blockIdx.x * 256 + threadIdx.x;
    if (i < BATCH * HEADS * 64 * 64) g_ctx[i] = 0.f;
    if (i < BATCH * DIM) g_qsum[i] = 0.f;
}

// ---------------- LayerNorm + transpose -> row-major fp16 ------------------
__global__ __launch_bounds__(256) void ln_kernel(
    const float* __restrict__ x, const float* __restrict__ lw,
    const float* __restrict__ lb)
{
    extern __shared__ float s[];               // [512][33]
    __shared__ float s_mu[32], s_rs[32];
    int tid = threadIdx.x;
    int token0 = blockIdx.x * 32;
    int b = token0 >> 13;
    int n0 = token0 & (SEQ - 1);
    const float* xb = x + (size_t)b * DIM * SEQ;

    #pragma unroll 4
    for (int i = 0; i < 64; i++) {
        int idx = i * 256 + tid;
        int d = idx >> 5, j = idx & 31;
        s[d * 33 + j] = xb[(size_t)d * SEQ + n0 + j];
    }
    __syncthreads();

    int w = tid >> 5, lane = tid & 31;
    for (int t = 0; t < 4; t++) {
        int j = w * 4 + t;
        float sum = 0.f, sq = 0.f;
        #pragma unroll
        for (int d = lane; d < DIM; d += 32) {
            float v = s[d * 33 + j];
            sum += v; sq += v * v;
        }
        #pragma unroll
        for (int o = 16; o; o >>= 1) {
            sum += __shfl_xor_sync(0xffffffffu, sum, o);
            sq  += __shfl_xor_sync(0xffffffffu, sq, o);
        }
        if (lane == 0) {
            float mu = sum * (1.f / DIM);
            float var = sq * (1.f / DIM) - mu * mu;
            s_mu[j] = mu;
            s_rs[j] = rsqrtf(var + 1e-5f);
        }
    }
    __syncthreads();

    #pragma unroll
    for (int it = 0; it < 8; it++) {
        int idx = it * 256 + tid;
        int g = idx & 63, j = idx >> 6;
        int d0 = g * 8;
        float mu = s_mu[j], rs = s_rs[j];
        union { __half h[8]; uint4 u; } ph;
        #pragma unroll
        for (int i = 0; i < 8; i++) {
            int d = d0 + i;
            float v = (s[d * 33 + j] - mu) * rs * lw[d] + lb[d];
            ph.h[i] = __float2half_rn(v);
        }
        *(uint4*)&g_a[(size_t)(token0 + j) * DIM + d0] = ph.u;
    }
}

// ---------------- weight fp32 -> fp16 ---------------------------------------
__global__ __launch_bounds__(256) void wconv_kernel(
    const float* __restrict__ wq, const float* __restrict__ wo)
{
    int stride = gridDim.x * 256;
    for (int i = blockIdx.x * 256 + threadIdx.x; i < DIM * QKVW; i += stride)
        g_wq[i] = __float2half_rn(wq[i]);
    for (int i = blockIdx.x * 256 + threadIdx.x; i < DIM * DIM; i += stride)
        g_wo[i] = __float2half_rn(wo[i]);
}

// ---------------- fp16 HMMA GEMM: C = A @ B, K=512 --------------------------
// BK=32 stages (two 16-k slices per stage), 16 iterations.
// mode 0: qkv output; q columns (<512) stored as exp(v*scale) + column sums.
// mode 1: out[b][dout][n] + bias (transposed store).
#define SLICE 10496              // A 6144 + B 4352
#define STAGE (2 * SLICE)        // 20992
__global__ __launch_bounds__(256) void mma_gemm_kernel(
    const __half* __restrict__ A, const __half* __restrict__ B,
    float* __restrict__ C, const float* __restrict__ bias, int ldb, int mode)
{
    extern __shared__ char smem[];
    uint32_t sb = s2u(smem);
    int tid = threadIdx.x, lane = tid & 31, wid = tid >> 5;
    int m0 = blockIdx.y * 128, n0 = blockIdx.x * 128;
    int wm = (wid >> 2) * 64, wn = (wid & 3) * 32;

    int ar = tid >> 1, ah8 = (tid & 1) * 8;
    int bkr = tid >> 4, bn8 = (tid & 15) * 8;
    const __half* Ag = A + (size_t)(m0 + ar) * DIM + ah8;
    const __half* Bg = B + (size_t)bkr * ldb + n0 + bn8;
    uint32_t dA = sb + ar * 48 + ah8 * 2;
    uint32_t dB = sb + 6144 + bkr * 272 + bn8 * 2;

    uint32_t aAddr[4], bAddr[4];
    #pragma unroll
    for (int mi = 0; mi < 4; mi++)
        aAddr[mi] = sb + (wm + mi * 16 + (lane & 15)) * 48 + (lane >> 4) * 16;
    #pragma unroll
    for (int ni = 0; ni < 4; ni++)
        bAddr[ni] = sb + 6144 + (lane & 15) * 272 + (wn + ni * 8) * 2;

    float d[4][4][4];
    #pragma unroll
    for (int mi = 0; mi < 4; mi++)
        #pragma unroll
        for (int ni = 0; ni < 4; ni++)
            #pragma unroll
            for (int r = 0; r < 4; r++) d[mi][ni][r] = 0.f;

    // prologue: stages 0,1 (each stage = 2 k16 slices)
    #pragma unroll
    for (int p = 0; p < 2; p++) {
        #pragma unroll
        for (int s = 0; s < 2; s++) {
            uint32_t so = p * STAGE + s * SLICE;
            int ks = p * 2 + s;
            CP16(dA + so, Ag + ks * 16);
            CP16(dB + so, Bg + (size_t)ks * 16 * ldb);
        }
        CPCOMMIT();
    }

    for (int kk = 0; kk < 16; kk++) {
        CPWAIT1();
        __syncthreads();
        if (kk + 2 < 16) {
            #pragma unroll
            for (int s = 0; s < 2; s++) {
                uint32_t so = ((kk + 2) % 3) * STAGE + s * SLICE;
                int ks = (kk + 2) * 2 + s;
                CP16(dA + so, Ag + ks * 16);
                CP16(dB + so, Bg + (size_t)ks * 16 * ldb);
            }
        }
        CPCOMMIT();

        #pragma unroll
        for (int s = 0; s < 2; s++) {
            uint32_t so = (kk % 3) * STAGE + s * SLICE;
            uint32_t ah[4][4], bh[4][2];
            #pragma unroll
            for (int mi = 0; mi < 4; mi++)
                LDSM_X4(ah[mi], aAddr[mi] + so);
            #pragma unroll
            for (int ni = 0; ni < 4; ni++)
                LDSM_X2T(bh[ni], bAddr[ni] + so);
            #pragma unroll
            for (int mi = 0; mi < 4; mi++)
                #pragma unroll
                for (int ni = 0; ni < 4; ni++)
                    MMA(d[mi][ni], ah[mi], bh[ni]);
        }
    }

    if (mode == 0) {
        bool isq = (n0 < 512);
        float* qs = (float*)smem;              // column partial sums (q tiles)
        if (isq) {
            __syncthreads();
            if (tid < 128) qs[tid] = 0.f;
            __syncthreads();
        }
        #pragma unroll
        for (int mi = 0; mi < 4; mi++) {
            int r0 = m0 + wm + mi * 16 + (lane >> 2);
            #pragma unroll
            for (int ni = 0; ni < 4; ni++) {
                int cl = wn + ni * 8 + (lane & 3) * 2;
                int c0 = n0 + cl;
                float v0 = d[mi][ni][0], v1 = d[mi][ni][1];
                float v2 = d[mi][ni][2], v3 = d[mi][ni][3];
                if (isq) {
                    v0 = __expf(v0 * SCALE_Q); v1 = __expf(v1 * SCALE_Q);
                    v2 = __expf(v2 * SCALE_Q); v3 = __expf(v3 * SCALE_Q);
                    atomicAdd(&qs[cl],     v0 + v2);
                    atomicAdd(&qs[cl + 1], v1 + v3);
                }
                *(float2*)&C[(size_t)r0 * ldb + c0]       = make_float2(v0, v1);
                *(float2*)&C[(size_t)(r0 + 8) * ldb + c0] = make_float2(v2, v3);
            }
        }
        if (isq) {
            __syncthreads();
            if (tid < 128)
                atomicAdd(&g_qsum[(m0 >> 13) * DIM + n0 + tid], qs[tid]);
        }
    } else {
        __syncthreads();
        float* st = (float*)smem;             // [128][PADT]
        #pragma unroll
        for (int mi = 0; mi < 4; mi++) {
            int r0 = wm + mi * 16 + (lane >> 2);
            #pragma unroll
            for (int ni = 0; ni < 4; ni++) {
                int c0 = wn + ni * 8 + (lane & 3) * 2;
                st[r0 * PADT + c0]           = d[mi][ni][0];
                st[r0 * PADT + c0 + 1]       = d[mi][ni][1];
                st[(r0 + 8) * PADT + c0]     = d[mi][ni][2];
                st[(r0 + 8) * PADT + c0 + 1] = d[mi][ni][3];
            }
        }
        __syncthreads();
        int b = m0 >> 13, nn0 = m0 & (SEQ - 1);
        float* dst = C + (size_t)b * DIM * SEQ + (size_t)n0 * SEQ + nn0;
        for (int idx = tid; idx < 16384; idx += 256) {
            int r = idx >> 7;
            int c = idx & 127;
            dst[(size_t)r * SEQ + c] = st[c * PADT + r] + bias[n0 + r];
        }
    }
}

// ---------------- k softmax + context accumulation --------------------------
__global__ __launch_bounds__(256) void ctx_kernel()
{
    __shared__ float kb[16][64];
    __shared__ float vb[16][64];
    int tid = threadIdx.x;
    int h = blockIdx.y;
    int tok0 = blockIdx.x * 512;
    int b = tok0 >> 13;
    int d = tid & 63, eg = tid >> 6;
    int ltt = tid >> 4, ld4 = (tid & 15) * 4;
    float acc[16] = {};

    for (int t0 = 0; t0 < 512; t0 += 16) {
        size_t base = (size_t)(tok0 + t0 + ltt) * QKVW + h * 64 + ld4;
        *(float4*)&kb[ltt][ld4] = *(const float4*)&g_qkv[base + 512];
        *(float4*)&vb[ltt][ld4] = *(const float4*)&g_qkv[base + 1024];
        __syncthreads();
        {
            int w = tid >> 5, lane = tid & 31;
            #pragma unroll
            for (int u = 0; u < 2; u++) {
                int tt = w * 2 + u;
                float e0 = __expf(kb[tt][lane]);
                float e1 = __expf(kb[tt][lane + 32]);
                float su = e0 + e1;
                #pragma unroll
                for (int o = 16; o; o >>= 1) su += __shfl_xor_sync(0xffffffffu, su, o);
                float inv = 1.f / su;
                kb[tt][lane] = e0 * inv;
                kb[tt][lane + 32] = e1 * inv;
            }
        }
        __syncthreads();
        #pragma unroll
        for (int tt = 0; tt < 16; tt++) {
            float a = kb[tt][d];
            const float4* vrow = (const float4*)&vb[tt][eg * 16];
            float4 w0 = vrow[0], w1 = vrow[1], w2 = vrow[2], w3 = vrow[3];
            acc[0]  += a * w0.x; acc[1]  += a * w0.y; acc[2]  += a * w0.z; acc[3]  += a * w0.w;
            acc[4]  += a * w1.x; acc[5]  += a * w1.y; acc[6]  += a * w1.z; acc[7]  += a * w1.w;
            acc[8]  += a * w2.x; acc[9]  += a * w2.y; acc[10] += a * w2.z; acc[11] += a * w2.w;
            acc[12] += a * w3.x; acc[13] += a * w3.y; acc[14] += a * w3.z; acc[15] += a * w3.w;
        }
        __syncthreads();
    }
    float* cdst = &g_ctx[((b * HEADS + h) * 64 + d) * 64 + eg * 16];
    #pragma unroll
    for (int c = 0; c < 16; c++) atomicAdd(&cdst[c], acc[c]);
}

// ---------------- o = qexp*rq @ ctx ; write row-major fp16 ------------------
__global__ __launch_bounds__(256) void oproj_kernel()
{
    __shared__ float cs[64][64];
    __shared__ float qt[64][65];
    __shared__ float rq[64];
    int tid = threadIdx.x;
    int h = blockIdx.y;
    int tok0 = blockIdx.x * 64;
    int b = tok0 >> 13;

    const float* csrc = &g_ctx[(b * HEADS + h) * 64 * 64];
    for (int i = tid; i < 4096; i += 256) cs[i >> 6][i & 63] = csrc[i];
    if (tid < 64) rq[tid] = 1.f / g_qsum[b * DIM + h * 64 + tid];
    __syncthreads();

    for (int i = tid; i < 64 * 64; i += 256) {
        int t = i >> 6, dd = i & 63;
        qt[t][dd] = g_qkv[(size_t)(tok0 + t) * QKVW + h * 64 + dd] * rq[dd];
    }
    __syncthreads();

    int tx = tid & 15, ty = tid >> 4;
    float acc[4][4] = {};
    #pragma unroll
    for (int dd = 0; dd < 64; dd++) {
        float a[4], bb[4];
        #pragma unroll
        for (int i = 0; i < 4; i++) a[i] = qt[ty * 4 + i][dd];
        #pragma unroll
        for (int j = 0; j < 4; j++) bb[j] = cs[dd][tx * 4 + j];
        #pragma unroll
        for (int i = 0; i < 4; i++)
            #pragma unroll
            for (int j = 0; j < 4; j++)
                acc[i][j] += a[i] * bb[j];
    }
    #pragma unroll
    for (int i = 0; i < 4; i++) {
        int t = tok0 + ty * 4 + i;
        union { __half h2[4]; uint2 u; } ph;
        #pragma unroll
        for (int j = 0; j < 4; j++)
            ph.h2[j] = __float2half_rn(acc[i][j]);
        *(uint2*)&g_o[(size_t)t * DIM + h * 64 + tx * 4] = ph.u;
    }
}

// ---------------- launch ------------------------------------------------------
extern "C" void kernel_launch(void* const* d_in, const int* in_sizes, int n_in,
                              void* d_out, int out_size)
{
    const float* x     = (const float*)d_in[0];
    const float* ln_w  = (const float*)d_in[1];
    const float* ln_b  = (const float*)d_in[2];
    const float* w_qkv = (const float*)d_in[3];
    const float* w_out = (const float*)d_in[4];
    const float* b_out = (const float*)d_in[5];
    float* out = (float*)d_out;

    __half *p_a, *p_o, *p_wq, *p_wo;
    float* p_qkv;
    cudaGetSymbolAddress((void**)&p_a, g_a);
    cudaGetSymbolAddress((void**)&p_o, g_o);
    cudaGetSymbolAddress((void**)&p_wq, g_wq);
    cudaGetSymbolAddress((void**)&p_wo, g_wo);
    cudaGetSymbolAddress((void**)&p_qkv, g_qkv);

    const int LN_SMEM   = 512 * 33 * 4;
    const int GEMM_SMEM = 128 * PADT * 4;    // 68096 >= 3*STAGE = 62976
    cudaFuncSetAttribute(ln_kernel, cudaFuncAttributeMaxDynamicSharedMemorySize, LN_SMEM);
    cudaFuncSetAttribute(mma_gemm_kernel, cudaFuncAttributeMaxDynamicSharedMemorySize, GEMM_SMEM);

    init_kernel<<<(BATCH * HEADS * 64 * 64 + 255) / 256, 256>>>();
    ln_kernel<<<NTOK / 32, 256, LN_SMEM>>>(x, ln_w, ln_b);
    wconv_kernel<<<1024, 256>>>(w_qkv, w_out);
    mma_gemm_kernel<<<dim3(QKVW / 128, MTILES), 256, GEMM_SMEM>>>(
        p_a, p_wq, p_qkv, nullptr, QKVW, 0);
    ctx_kernel<<<dim3(NTOK / 512, HEADS), 256>>>();
    oproj_kernel<<<dim3(NTOK / 64, HEADS), 256>>>();
    mma_gemm_kernel<<<dim3(DIM / 128, MTILES), 256, GEMM_SMEM>>>(
        p_o, p_wo, out, b_out, DIM, 1);
}